// round 2
// baseline (speedup 1.0000x reference)
#include <cuda_runtime.h>
#include <cstdint>

// Problem constants (fixed by setup_inputs)
static constexpr int B    = 16;
static constexpr int H    = 256;
static constexpr int W    = 256;
static constexpr int CIN0 = 3;
static constexpr int CMID = 16;
static constexpr int COUT = 64;
static constexpr float BN_EPS = 1e-5f;

// Scratch: intermediates + BN stats. __device__ globals (no runtime allocation).
__device__ float g_h1[(size_t)B * CMID * H * W];   // 64 MB
__device__ float g_h2[(size_t)B * CMID * H * W];   // 64 MB
__device__ float g_stats[2 * COUT];                // [0:64) sum, [64:128) sumsq
__device__ float g_scale[COUT];
__device__ float g_shift[COUT];

// ---- packed fp32x2 helpers (Blackwell f32x2 pipe; FFMA2 not emitted by ptxas
//      from plain C++, only via inline PTX) --------------------------------
using u64 = unsigned long long;

__device__ __forceinline__ u64 pack2(float lo, float hi) {
    u64 r;
    asm("mov.b64 %0, {%1, %2};" : "=l"(r) : "f"(lo), "f"(hi));
    return r;
}
__device__ __forceinline__ u64 ffma2(u64 a, u64 b, u64 c) {
    u64 d;
    asm("fma.rn.f32x2 %0, %1, %2, %3;" : "=l"(d) : "l"(a), "l"(b), "l"(c));
    return d;
}
__device__ __forceinline__ float2 unpack2(u64 v) {
    float2 f;
    asm("mov.b64 {%0, %1}, %2;" : "=f"(f.x), "=f"(f.y) : "l"(v));
    return f;
}

// ---------------------------------------------------------------------------
// Tiled direct 3x3 conv (pad 1, stride 1), NCHW, fp32x2-packed accumulators.
// Block computes a TH x TW output tile for all CO channels of one batch image.
// Thread register tile: 8 consecutive-x pixels (4 f32x2 pairs) x 8 out chans.
// smem: input tile with halo (CI x (TH+2) x RS) + weights DUPLICATED as
// (w,w) float2 pairs, laid out [k][co], so the FFMA2 multiplier is loaded
// pre-packed via warp-uniform (broadcast) LDS.128.
// STATS: fuse BN sum/sumsq (requires NPX == 32: full warp shares a co-group —
// true for the conv3 instantiation).
// ---------------------------------------------------------------------------
template <int CI, int CO, int TH, int TW, bool STATS>
__global__ void __launch_bounds__(256, 2)
conv3x3_tile(const float* __restrict__ in, const float* __restrict__ wgt,
             float* __restrict__ out)
{
    constexpr int NT  = 256;
    constexpr int NPX = TH * TW / 8;      // pixel slots (8 px each)
    constexpr int NCG = CO / 8;           // channel groups (8 co each)
    static_assert(NPX * NCG == NT, "thread shape mismatch");
    constexpr int IH = TH + 2;
    constexpr int IW = TW + 2;
    constexpr int RS = (IW + 3) & ~3;     // row stride, 16B-aligned rows

    extern __shared__ float smem[];
    float*  s_in = smem;                      // CI * IH * RS floats
    float2* s_w  = (float2*)(smem + CI * IH * RS);  // CI*9*CO float2 (dup pairs)

    const int tid = threadIdx.x;
    const int tiles_x = W / TW;
    const int tiles_y = H / TH;
    int bid = blockIdx.x;
    const int tx = bid % tiles_x; bid /= tiles_x;
    const int ty = bid % tiles_y; bid /= tiles_y;
    const int b  = bid;

    // Stage weights duplicated: global w[co][ci][dy][dx] ->
    // smem s_w[(ci*9+t)*CO + co] = (w, w)
    for (int i = tid; i < CI * 9 * CO; i += NT) {
        const int k  = i / CO;
        const int co = i - k * CO;
        const int ci = k / 9;
        const int t  = k - ci * 9;
        const float w = wgt[(co * CI + ci) * 9 + t];
        s_w[i] = make_float2(w, w);
    }

    // Stage input tile with halo, zero-padded at image borders.
    const float* inb = in + (size_t)b * CI * H * W;
    const int gy0 = ty * TH - 1;
    const int gx0 = tx * TW - 1;
    for (int i = tid; i < CI * IH * IW; i += NT) {
        const int ci = i / (IH * IW);
        int r = i - ci * IH * IW;
        const int y = r / IW;
        const int x = r - y * IW;
        const int gy = gy0 + y, gx = gx0 + x;
        float v = 0.f;
        if (gy >= 0 && gy < H && gx >= 0 && gx < W)
            v = inb[(ci * H + gy) * W + gx];
        s_in[(ci * IH + y) * RS + x] = v;
    }
    __syncthreads();

    const int px_slot = tid % NPX;            // warp-uniform co-group layout
    const int cg      = tid / NPX;
    const int py      = px_slot / (TW / 8);
    const int x0      = (px_slot - py * (TW / 8)) * 8;
    const int co0     = cg * 8;

    u64 acc[8][4];                             // [co][px-pair], f32x2 packed
    #pragma unroll
    for (int i = 0; i < 8; ++i)
        #pragma unroll
        for (int j = 0; j < 4; ++j) acc[i][j] = 0ull;

    #pragma unroll 1                           // keep code size I$-friendly
    for (int ci = 0; ci < CI; ++ci) {
        #pragma unroll
        for (int dy = 0; dy < 3; ++dy) {
            // Load the 10-wide input row once; build the 9 sliding pairs.
            const float* rowp = &s_in[(ci * IH + py + dy) * RS + x0];
            float rr[10];
            const float4 a0 = *reinterpret_cast<const float4*>(rowp);
            const float4 a1 = *reinterpret_cast<const float4*>(rowp + 4);
            const float2 a2 = *reinterpret_cast<const float2*>(rowp + 8);
            rr[0] = a0.x; rr[1] = a0.y; rr[2] = a0.z; rr[3] = a0.w;
            rr[4] = a1.x; rr[5] = a1.y; rr[6] = a1.z; rr[7] = a1.w;
            rr[8] = a2.x; rr[9] = a2.y;
            u64 rp[9];
            #pragma unroll
            for (int k = 0; k < 9; ++k) rp[k] = pack2(rr[k], rr[k + 1]);

            #pragma unroll
            for (int dx = 0; dx < 3; ++dx) {
                const ulonglong2* wp = reinterpret_cast<const ulonglong2*>(
                    &s_w[(ci * 9 + dy * 3 + dx) * CO + co0]);
                const ulonglong2 q0 = wp[0];
                const ulonglong2 q1 = wp[1];
                const ulonglong2 q2 = wp[2];
                const ulonglong2 q3 = wp[3];
                const u64 wv[8] = {q0.x, q0.y, q1.x, q1.y,
                                   q2.x, q2.y, q3.x, q3.y};
                #pragma unroll
                for (int co = 0; co < 8; ++co)
                    #pragma unroll
                    for (int p = 0; p < 4; ++p)
                        acc[co][p] = ffma2(rp[2 * p + dx], wv[co], acc[co][p]);
            }
        }
    }

    // Store: pair layout == pixel order, so 2x 16B stores per co row.
    float* outb = out + (size_t)b * CO * H * W;
    const int oy = ty * TH + py;
    const int ox = tx * TW + x0;
    #pragma unroll
    for (int co = 0; co < 8; ++co) {
        u64* op = reinterpret_cast<u64*>(
            &outb[((size_t)(co0 + co) * H + oy) * W + ox]);
        *reinterpret_cast<ulonglong2*>(op) =
            make_ulonglong2(acc[co][0], acc[co][1]);
        *reinterpret_cast<ulonglong2*>(op + 2) =
            make_ulonglong2(acc[co][2], acc[co][3]);
    }

    if (STATS) {
        // Entire warp shares one co-group (NPX == 32): shuffle-reduce per co.
        #pragma unroll
        for (int co = 0; co < 8; ++co) {
            float s = 0.f, q = 0.f;
            #pragma unroll
            for (int p = 0; p < 4; ++p) {
                const float2 v = unpack2(acc[co][p]);
                s += v.x + v.y;
                q = fmaf(v.x, v.x, q);
                q = fmaf(v.y, v.y, q);
            }
            #pragma unroll
            for (int off = 16; off > 0; off >>= 1) {
                s += __shfl_xor_sync(0xffffffffu, s, off);
                q += __shfl_xor_sync(0xffffffffu, q, off);
            }
            if ((tid & 31) == 0) {
                atomicAdd(&g_stats[co0 + co], s);
                atomicAdd(&g_stats[COUT + co0 + co], q);
            }
        }
    }
}

__global__ void zero_stats_kernel()
{
    if (threadIdx.x < 2 * COUT) g_stats[threadIdx.x] = 0.f;
}

__global__ void bn_finalize_kernel(const float* __restrict__ gamma,
                                   const float* __restrict__ beta)
{
    const int c = threadIdx.x;
    if (c >= COUT) return;
    const float n    = (float)B * (float)H * (float)W;  // 1,048,576
    const float mean = g_stats[c] / n;
    const float var  = g_stats[COUT + c] / n - mean * mean;
    const float sc   = gamma[c] * rsqrtf(var + BN_EPS);
    g_scale[c] = sc;
    g_shift[c] = beta[c] - mean * sc;
}

// In-place normalize of d_out, vectorized float4. Per channel there are
// 65536/4 = 16384 float4s, so (idx >> 14) & 63 is the channel (block-uniform).
__global__ void bn_apply_kernel(float* __restrict__ out)
{
    const int idx = blockIdx.x * blockDim.x + threadIdx.x;   // float4 index
    const int c = (idx >> 14) & (COUT - 1);
    const float sc = g_scale[c];
    const float sh = g_shift[c];
    float4 v = reinterpret_cast<float4*>(out)[idx];
    v.x = fmaf(v.x, sc, sh);
    v.y = fmaf(v.y, sc, sh);
    v.z = fmaf(v.z, sc, sh);
    v.w = fmaf(v.w, sc, sh);
    reinterpret_cast<float4*>(out)[idx] = v;
}

extern "C" void kernel_launch(void* const* d_in, const int* in_sizes, int n_in,
                              void* d_out, int out_size)
{
    (void)in_sizes; (void)n_in; (void)out_size;
    const float* x     = (const float*)d_in[0];
    const float* w1    = (const float*)d_in[1];
    const float* w2    = (const float*)d_in[2];
    const float* w3    = (const float*)d_in[3];
    const float* gamma = (const float*)d_in[4];
    const float* beta  = (const float*)d_in[5];
    float* out = (float*)d_out;

    float *h1, *h2;
    cudaGetSymbolAddress((void**)&h1, g_h1);
    cudaGetSymbolAddress((void**)&h2, g_h2);

    auto* k1 = conv3x3_tile<CIN0, CMID, 32, 32, false>;
    auto* k2 = conv3x3_tile<CMID, CMID, 32, 32, false>;
    auto* k3 = conv3x3_tile<CMID, COUT, 16, 16, true>;

    // smem bytes: input tile (fp32) + duplicated weight pairs (float2)
    constexpr int SM1 = CIN0 * 34 * 36 * 4 + CIN0 * 9 * CMID * 8;   // 18,144 B
    constexpr int SM2 = CMID * 34 * 36 * 4 + CMID * 9 * CMID * 8;   // 96,768 B
    constexpr int SM3 = CMID * 18 * 20 * 4 + CMID * 9 * COUT * 8;   // 96,768 B

    cudaFuncSetAttribute(k1, cudaFuncAttributeMaxDynamicSharedMemorySize, SM1);
    cudaFuncSetAttribute(k2, cudaFuncAttributeMaxDynamicSharedMemorySize, SM2);
    cudaFuncSetAttribute(k3, cudaFuncAttributeMaxDynamicSharedMemorySize, SM3);

    zero_stats_kernel<<<1, 128>>>();
    k1<<<B * (H / 32) * (W / 32), 256, SM1>>>(x,  w1, h1);
    k2<<<B * (H / 32) * (W / 32), 256, SM2>>>(h1, w2, h2);
    k3<<<B * (H / 16) * (W / 16), 256, SM3>>>(h2, w3, out);
    bn_finalize_kernel<<<1, 64>>>(gamma, beta);
    bn_apply_kernel<<<(B * COUT * H * W / 4) / 256, 256>>>(out);
}

// round 3
// speedup vs baseline: 1.0024x; 1.0024x over previous
#include <cuda_runtime.h>
#include <cstdint>

// Problem constants (fixed by setup_inputs)
static constexpr int B    = 16;
static constexpr int H    = 256;
static constexpr int W    = 256;
static constexpr int CIN0 = 3;
static constexpr int CMID = 16;
static constexpr int COUT = 64;
static constexpr float BN_EPS = 1e-5f;

// Scratch: intermediates + BN stats. __device__ globals (no runtime allocation).
__device__ float g_h1[(size_t)B * CMID * H * W];   // 64 MB
__device__ float g_h2[(size_t)B * CMID * H * W];   // 64 MB
__device__ float g_stats[2 * COUT];                // [0:64) sum, [64:128) sumsq
__device__ float g_scale[COUT];
__device__ float g_shift[COUT];

// ---- packed fp32x2 helpers (Blackwell f32x2 pipe; FFMA2 not emitted by ptxas
//      from plain C++, only via inline PTX) --------------------------------
using u64 = unsigned long long;

__device__ __forceinline__ u64 pack2(float lo, float hi) {
    u64 r;
    asm("mov.b64 %0, {%1, %2};" : "=l"(r) : "f"(lo), "f"(hi));
    return r;
}
__device__ __forceinline__ u64 ffma2(u64 a, u64 b, u64 c) {
    u64 d;
    asm("fma.rn.f32x2 %0, %1, %2, %3;" : "=l"(d) : "l"(a), "l"(b), "l"(c));
    return d;
}
__device__ __forceinline__ float2 unpack2(u64 v) {
    float2 f;
    asm("mov.b64 {%0, %1}, %2;" : "=f"(f.x), "=f"(f.y) : "l"(v));
    return f;
}

// ---------------------------------------------------------------------------
// Tiled direct 3x3 conv (pad 1, stride 1), NCHW, fp32x2-packed accumulators.
// Block computes a TH x TW output tile for all CO channels of one batch image.
// Thread register tile: 8 consecutive-x pixels (4 f32x2 pairs) x 8 out chans.
// smem: input tile with halo (CI x (TH+2) x RS) + weights DUPLICATED as
// (w,w) float2 pairs, laid out [k][co], so the FFMA2 multiplier is loaded
// pre-packed via warp-uniform (broadcast) LDS.128.
// STATS: fuse BN sum/sumsq (requires NPX == 32: full warp shares a co-group —
// true for the conv3 instantiation).
// ---------------------------------------------------------------------------
template <int CI, int CO, int TH, int TW, bool STATS>
__global__ void __launch_bounds__(256, 2)
conv3x3_tile(const float* __restrict__ in, const float* __restrict__ wgt,
             float* __restrict__ out)
{
    constexpr int NT  = 256;
    constexpr int NPX = TH * TW / 8;      // pixel slots (8 px each)
    constexpr int NCG = CO / 8;           // channel groups (8 co each)
    static_assert(NPX * NCG == NT, "thread shape mismatch");
    constexpr int IH = TH + 2;
    constexpr int IW = TW + 2;
    constexpr int RS = (IW + 3) & ~3;     // row stride, 16B-aligned rows

    extern __shared__ float smem[];
    float*  s_in = smem;                      // CI * IH * RS floats
    float2* s_w  = (float2*)(smem + CI * IH * RS);  // CI*9*CO float2 (dup pairs)

    const int tid = threadIdx.x;
    const int tiles_x = W / TW;
    const int tiles_y = H / TH;
    int bid = blockIdx.x;
    const int tx = bid % tiles_x; bid /= tiles_x;
    const int ty = bid % tiles_y; bid /= tiles_y;
    const int b  = bid;

    // Stage weights duplicated: global w[co][ci][dy][dx] ->
    // smem s_w[(ci*9+t)*CO + co] = (w, w)
    for (int i = tid; i < CI * 9 * CO; i += NT) {
        const int k  = i / CO;
        const int co = i - k * CO;
        const int ci = k / 9;
        const int t  = k - ci * 9;
        const float w = wgt[(co * CI + ci) * 9 + t];
        s_w[i] = make_float2(w, w);
    }

    // Stage input tile with halo, zero-padded at image borders.
    const float* inb = in + (size_t)b * CI * H * W;
    const int gy0 = ty * TH - 1;
    const int gx0 = tx * TW - 1;
    for (int i = tid; i < CI * IH * IW; i += NT) {
        const int ci = i / (IH * IW);
        int r = i - ci * IH * IW;
        const int y = r / IW;
        const int x = r - y * IW;
        const int gy = gy0 + y, gx = gx0 + x;
        float v = 0.f;
        if (gy >= 0 && gy < H && gx >= 0 && gx < W)
            v = inb[(ci * H + gy) * W + gx];
        s_in[(ci * IH + y) * RS + x] = v;
    }
    __syncthreads();

    const int px_slot = tid % NPX;            // warp-uniform co-group layout
    const int cg      = tid / NPX;
    const int py      = px_slot / (TW / 8);
    const int x0      = (px_slot - py * (TW / 8)) * 8;
    const int co0     = cg * 8;

    u64 acc[8][4];                             // [co][px-pair], f32x2 packed
    #pragma unroll
    for (int i = 0; i < 8; ++i)
        #pragma unroll
        for (int j = 0; j < 4; ++j) acc[i][j] = 0ull;

    #pragma unroll 1                           // keep code size I$-friendly
    for (int ci = 0; ci < CI; ++ci) {
        #pragma unroll
        for (int dy = 0; dy < 3; ++dy) {
            // Load the 10-wide input row once; build the 9 sliding pairs.
            const float* rowp = &s_in[(ci * IH + py + dy) * RS + x0];
            float rr[10];
            const float4 a0 = *reinterpret_cast<const float4*>(rowp);
            const float4 a1 = *reinterpret_cast<const float4*>(rowp + 4);
            const float2 a2 = *reinterpret_cast<const float2*>(rowp + 8);
            rr[0] = a0.x; rr[1] = a0.y; rr[2] = a0.z; rr[3] = a0.w;
            rr[4] = a1.x; rr[5] = a1.y; rr[6] = a1.z; rr[7] = a1.w;
            rr[8] = a2.x; rr[9] = a2.y;
            u64 rp[9];
            #pragma unroll
            for (int k = 0; k < 9; ++k) rp[k] = pack2(rr[k], rr[k + 1]);

            #pragma unroll
            for (int dx = 0; dx < 3; ++dx) {
                const ulonglong2* wp = reinterpret_cast<const ulonglong2*>(
                    &s_w[(ci * 9 + dy * 3 + dx) * CO + co0]);
                const ulonglong2 q0 = wp[0];
                const ulonglong2 q1 = wp[1];
                const ulonglong2 q2 = wp[2];
                const ulonglong2 q3 = wp[3];
                const u64 wv[8] = {q0.x, q0.y, q1.x, q1.y,
                                   q2.x, q2.y, q3.x, q3.y};
                #pragma unroll
                for (int co = 0; co < 8; ++co)
                    #pragma unroll
                    for (int p = 0; p < 4; ++p)
                        acc[co][p] = ffma2(rp[2 * p + dx], wv[co], acc[co][p]);
            }
        }
    }

    // Store: pair layout == pixel order, so 2x 16B stores per co row.
    float* outb = out + (size_t)b * CO * H * W;
    const int oy = ty * TH + py;
    const int ox = tx * TW + x0;
    #pragma unroll
    for (int co = 0; co < 8; ++co) {
        u64* op = reinterpret_cast<u64*>(
            &outb[((size_t)(co0 + co) * H + oy) * W + ox]);
        *reinterpret_cast<ulonglong2*>(op) =
            make_ulonglong2(acc[co][0], acc[co][1]);
        *reinterpret_cast<ulonglong2*>(op + 2) =
            make_ulonglong2(acc[co][2], acc[co][3]);
    }

    if (STATS) {
        // Entire warp shares one co-group (NPX == 32): shuffle-reduce per co.
        #pragma unroll
        for (int co = 0; co < 8; ++co) {
            float s = 0.f, q = 0.f;
            #pragma unroll
            for (int p = 0; p < 4; ++p) {
                const float2 v = unpack2(acc[co][p]);
                s += v.x + v.y;
                q = fmaf(v.x, v.x, q);
                q = fmaf(v.y, v.y, q);
            }
            #pragma unroll
            for (int off = 16; off > 0; off >>= 1) {
                s += __shfl_xor_sync(0xffffffffu, s, off);
                q += __shfl_xor_sync(0xffffffffu, q, off);
            }
            if ((tid & 31) == 0) {
                atomicAdd(&g_stats[co0 + co], s);
                atomicAdd(&g_stats[COUT + co0 + co], q);
            }
        }
    }
}

__global__ void zero_stats_kernel()
{
    if (threadIdx.x < 2 * COUT) g_stats[threadIdx.x] = 0.f;
}

__global__ void bn_finalize_kernel(const float* __restrict__ gamma,
                                   const float* __restrict__ beta)
{
    const int c = threadIdx.x;
    if (c >= COUT) return;
    const float n    = (float)B * (float)H * (float)W;  // 1,048,576
    const float mean = g_stats[c] / n;
    const float var  = g_stats[COUT + c] / n - mean * mean;
    const float sc   = gamma[c] * rsqrtf(var + BN_EPS);
    g_scale[c] = sc;
    g_shift[c] = beta[c] - mean * sc;
}

// In-place normalize of d_out, vectorized float4. Per channel there are
// 65536/4 = 16384 float4s, so (idx >> 14) & 63 is the channel (block-uniform).
__global__ void bn_apply_kernel(float* __restrict__ out)
{
    const int idx = blockIdx.x * blockDim.x + threadIdx.x;   // float4 index
    const int c = (idx >> 14) & (COUT - 1);
    const float sc = g_scale[c];
    const float sh = g_shift[c];
    float4 v = reinterpret_cast<float4*>(out)[idx];
    v.x = fmaf(v.x, sc, sh);
    v.y = fmaf(v.y, sc, sh);
    v.z = fmaf(v.z, sc, sh);
    v.w = fmaf(v.w, sc, sh);
    reinterpret_cast<float4*>(out)[idx] = v;
}

extern "C" void kernel_launch(void* const* d_in, const int* in_sizes, int n_in,
                              void* d_out, int out_size)
{
    (void)in_sizes; (void)n_in; (void)out_size;
    const float* x     = (const float*)d_in[0];
    const float* w1    = (const float*)d_in[1];
    const float* w2    = (const float*)d_in[2];
    const float* w3    = (const float*)d_in[3];
    const float* gamma = (const float*)d_in[4];
    const float* beta  = (const float*)d_in[5];
    float* out = (float*)d_out;

    float *h1, *h2;
    cudaGetSymbolAddress((void**)&h1, g_h1);
    cudaGetSymbolAddress((void**)&h2, g_h2);

    auto* k1 = conv3x3_tile<CIN0, CMID, 32, 32, false>;
    auto* k2 = conv3x3_tile<CMID, CMID, 32, 32, false>;
    auto* k3 = conv3x3_tile<CMID, COUT, 16, 16, true>;

    // smem bytes: input tile (fp32) + duplicated weight pairs (float2)
    constexpr int SM1 = CIN0 * 34 * 36 * 4 + CIN0 * 9 * CMID * 8;   // 18,144 B
    constexpr int SM2 = CMID * 34 * 36 * 4 + CMID * 9 * CMID * 8;   // 96,768 B
    constexpr int SM3 = CMID * 18 * 20 * 4 + CMID * 9 * COUT * 8;   // 96,768 B

    cudaFuncSetAttribute(k1, cudaFuncAttributeMaxDynamicSharedMemorySize, SM1);
    cudaFuncSetAttribute(k2, cudaFuncAttributeMaxDynamicSharedMemorySize, SM2);
    cudaFuncSetAttribute(k3, cudaFuncAttributeMaxDynamicSharedMemorySize, SM3);

    zero_stats_kernel<<<1, 128>>>();
    k1<<<B * (H / 32) * (W / 32), 256, SM1>>>(x,  w1, h1);
    k2<<<B * (H / 32) * (W / 32), 256, SM2>>>(h1, w2, h2);
    k3<<<B * (H / 16) * (W / 16), 256, SM3>>>(h2, w3, out);
    bn_finalize_kernel<<<1, 64>>>(gamma, beta);
    bn_apply_kernel<<<(B * COUT * H * W / 4) / 256, 256>>>(out);
}

// round 6
// speedup vs baseline: 1.5653x; 1.5616x over previous
#include <cuda_runtime.h>
#include <cuda_bf16.h>
#include <cstdint>

static constexpr int B = 16, H = 256, W = 256;
static constexpr int CIN0 = 3, CMID = 16, COUT = 64;
static constexpr float BN_EPS = 1e-5f;

__device__ float g_h1[(size_t)B * CMID * H * W];
__device__ float g_h2[(size_t)B * CMID * H * W];
__device__ float g_stats[2 * COUT];
__device__ float g_scale[COUT];
__device__ float g_shift[COUT];

// ---- smem asm helpers ------------------------------------------------------
__device__ __forceinline__ uint32_t smem_u32(const void* p) {
    uint32_t a;
    asm("{ .reg .u64 t; cvta.to.shared.u64 t, %1; cvt.u32.u64 %0, t; }"
        : "=r"(a) : "l"(p));
    return a;
}
__device__ __forceinline__ void sts64(uint32_t a, uint32_t x, uint32_t y) {
    asm volatile("st.shared.v2.u32 [%0], {%1,%2};" :: "r"(a), "r"(x), "r"(y));
}
__device__ __forceinline__ void sts16(uint32_t a, uint16_t v) {
    asm volatile("st.shared.u16 [%0], %1;" :: "r"(a), "h"(v));
}
__device__ __forceinline__ uint32_t lds32(uint32_t a) {
    uint32_t v;
    asm volatile("ld.shared.b32 %0, [%1];" : "=r"(v) : "r"(a));
    return v;
}
// baseline-PTX bf16 tensor-core mma (sm_80+; no 'a'-gated features)
__device__ __forceinline__ void mma_bf16(float d[4], const uint32_t a[4],
                                         const uint32_t b[2]) {
    asm volatile(
        "mma.sync.aligned.m16n8k16.row.col.f32.bf16.bf16.f32 "
        "{%0,%1,%2,%3},{%4,%5,%6,%7},{%8,%9},{%0,%1,%2,%3};"
        : "+f"(d[0]), "+f"(d[1]), "+f"(d[2]), "+f"(d[3])
        : "r"(a[0]), "r"(a[1]), "r"(a[2]), "r"(a[3]), "r"(b[0]), "r"(b[1]));
}

// ---- conv3 via mma.sync -----------------------------------------------------
// A tile per input row: [128 px][K=48 bf16], row stride 56 bf16 (112 B,
// conflict-free for fragment LDS). Ring of 4 rows, hi & lo halves.
// B tile per dy: [64 co][48], same stride, hi & lo halves.
static constexpr int ASLOT = 28672;             // hi(14336) + lo(14336)
static constexpr int ALO   = 14336;
static constexpr int BBASE = 4 * ASLOT;         // 114688
static constexpr int BDY   = 14336;             // hi(7168) + lo(7168)
static constexpr int BLO   = 7168;
static constexpr int SOFF  = BBASE + 3 * BDY;   // 157696: 128 floats of stats
static constexpr int SMEM3 = SOFF + 512;
static constexpr int NY    = 8;

__device__ __forceinline__ void stage_row(uint32_t s32, const float* in,
                                          int b, int yin, int x0, int tid) {
    const uint32_t Ah = s32 + (uint32_t)(yin & 3) * ASLOT;
    for (int it = tid; it < 520; it += 256) {
        const int cig = it / 130, xl = it - cig * 130, xin = x0 - 1 + xl;
        uint32_t hb[4], lb[4];
        #pragma unroll
        for (int j = 0; j < 4; ++j) {
            const int ci = cig * 4 + j;
            float v = (xin >= 0 && xin < W)
                    ? in[(((size_t)b * CMID + ci) * H + yin) * W + xin] : 0.f;
            __nv_bfloat16 h = __float2bfloat16_rn(v);
            __nv_bfloat16 l = __float2bfloat16_rn(v - __bfloat162float(h));
            hb[j] = __bfloat16_as_ushort(h);
            lb[j] = __bfloat16_as_ushort(l);
        }
        const uint32_t h0 = hb[0] | (hb[1] << 16), h1 = hb[2] | (hb[3] << 16);
        const uint32_t l0 = lb[0] | (lb[1] << 16), l1 = lb[2] | (lb[3] << 16);
        #pragma unroll
        for (int dx = 0; dx < 3; ++dx) {
            const int r = xl - dx;
            if (r < 0 || r >= 128) continue;
            const uint32_t off = (uint32_t)(r * 112 + (dx * 16 + cig * 4) * 2);
            sts64(Ah + off, h0, h1);
            sts64(Ah + ALO + off, l0, l1);
        }
    }
}

__global__ void __launch_bounds__(256, 1)
conv3_mma(const float* __restrict__ in, const float* __restrict__ w3,
          float* __restrict__ out) {
    extern __shared__ char sm[];
    const uint32_t s32 = smem_u32(sm);
    float* sstats = (float*)(sm + SOFF);
    const int tid = threadIdx.x, wid = tid >> 5, lid = tid & 31;
    const int g = lid >> 2, tig = lid & 3;
    int bid = blockIdx.x;
    const int xs = bid & 1, ys = (bid >> 1) & 31, b = bid >> 6;
    const int x0 = xs * 128, y0 = ys * NY;

    if (tid < 128) sstats[tid] = 0.f;
    for (int i = tid; i < COUT * CMID * 9; i += 256) {   // 9216 weights -> B tiles
        const int dx = i % 3; int t = i / 3;
        const int dy = t % 3; t /= 3;
        const int ci = t & 15, co = t >> 4;
        const float v = w3[((co * CMID + ci) * 3 + dy) * 3 + dx];
        __nv_bfloat16 h = __float2bfloat16_rn(v);
        __nv_bfloat16 l = __float2bfloat16_rn(v - __bfloat162float(h));
        const uint32_t a = s32 + BBASE + dy * BDY + co * 112 + (dx * 16 + ci) * 2;
        sts16(a, (uint16_t)__bfloat16_as_ushort(h));
        sts16(a + BLO, (uint16_t)__bfloat16_as_ushort(l));
    }
    if (y0 > 0) stage_row(s32, in, b, y0 - 1, x0, tid);
    stage_row(s32, in, b, y0, x0, tid);

    const int wm = wid & 3, wn = wid >> 2;
    float sacc[4][2] = {}, qacc[4][2] = {};

    for (int i = 0; i < NY; ++i) {
        const int y = y0 + i;
        if (y + 1 < H) stage_row(s32, in, b, y + 1, x0, tid);
        __syncthreads();

        float acc[2][4][4];
        #pragma unroll
        for (int mf = 0; mf < 2; ++mf)
            #pragma unroll
            for (int nf = 0; nf < 4; ++nf)
                #pragma unroll
                for (int r = 0; r < 4; ++r) acc[mf][nf][r] = 0.f;

        #pragma unroll
        for (int dy = 0; dy < 3; ++dy) {
            const int yin = y - 1 + dy;
            if (yin < 0 || yin >= H) continue;
            const uint32_t A0 = s32 + (uint32_t)(yin & 3) * ASLOT;
            const uint32_t B0 = s32 + BBASE + dy * BDY;
            #pragma unroll
            for (int ks = 0; ks < 3; ++ks) {
                uint32_t ah[2][4], al[2][4], bh[4][2], bl[4][2];
                #pragma unroll
                for (int mf = 0; mf < 2; ++mf) {
                    const uint32_t r0 = A0 +
                        (uint32_t)((wm * 32 + mf * 16 + g) * 112 + ks * 32 + tig * 4);
                    const uint32_t r1 = r0 + 8 * 112;
                    ah[mf][0] = lds32(r0);        ah[mf][1] = lds32(r1);
                    ah[mf][2] = lds32(r0 + 16);   ah[mf][3] = lds32(r1 + 16);
                    al[mf][0] = lds32(r0 + ALO);  al[mf][1] = lds32(r1 + ALO);
                    al[mf][2] = lds32(r0 + ALO + 16);
                    al[mf][3] = lds32(r1 + ALO + 16);
                }
                #pragma unroll
                for (int nf = 0; nf < 4; ++nf) {
                    const uint32_t c0 = B0 +
                        (uint32_t)((wn * 32 + nf * 8 + g) * 112 + ks * 32 + tig * 4);
                    bh[nf][0] = lds32(c0);        bh[nf][1] = lds32(c0 + 16);
                    bl[nf][0] = lds32(c0 + BLO);  bl[nf][1] = lds32(c0 + BLO + 16);
                }
                #pragma unroll
                for (int mf = 0; mf < 2; ++mf)
                    #pragma unroll
                    for (int nf = 0; nf < 4; ++nf) {
                        mma_bf16(acc[mf][nf], ah[mf], bh[nf]);
                        mma_bf16(acc[mf][nf], ah[mf], bl[nf]);
                        mma_bf16(acc[mf][nf], al[mf], bh[nf]);
                    }
            }
        }

        #pragma unroll
        for (int mf = 0; mf < 2; ++mf) {
            const int x = x0 + wm * 32 + mf * 16 + g;
            #pragma unroll
            for (int nf = 0; nf < 4; ++nf) {
                const int co = wn * 32 + nf * 8 + tig * 2;
                float* p0 = out + (((size_t)b * COUT + co) * H + y) * W + x;
                float* p1 = p0 + (size_t)H * W;
                const float v0 = acc[mf][nf][0], v1 = acc[mf][nf][1];
                const float v2 = acc[mf][nf][2], v3 = acc[mf][nf][3];
                p0[0] = v0; p1[0] = v1; p0[8] = v2; p1[8] = v3;
                sacc[nf][0] += v0 + v2;
                sacc[nf][1] += v1 + v3;
                qacc[nf][0] = fmaf(v0, v0, fmaf(v2, v2, qacc[nf][0]));
                qacc[nf][1] = fmaf(v1, v1, fmaf(v3, v3, qacc[nf][1]));
            }
        }
    }

    #pragma unroll
    for (int nf = 0; nf < 4; ++nf)
        #pragma unroll
        for (int j = 0; j < 2; ++j) {
            float s = sacc[nf][j], q = qacc[nf][j];
            #pragma unroll
            for (int o = 4; o < 32; o <<= 1) {   // reduce over g (same tig)
                s += __shfl_xor_sync(0xffffffffu, s, o);
                q += __shfl_xor_sync(0xffffffffu, q, o);
            }
            if (g == 0) {
                const int c = wn * 32 + nf * 8 + tig * 2 + j;
                atomicAdd(&sstats[c], s);
                atomicAdd(&sstats[COUT + c], q);
            }
        }
    __syncthreads();
    if (tid < 128) atomicAdd(&g_stats[tid], sstats[tid]);
}

// ---- scalar tiled conv (R1) for conv1/conv2 -------------------------------
template <int CI, int CO, int TH, int TW>
__global__ void __launch_bounds__(256, 2)
conv3x3_tile(const float* __restrict__ in, const float* __restrict__ wgt,
             float* __restrict__ out) {
    constexpr int NT = 256, NPX = TH * TW / 8, NCG = CO / 8;
    static_assert(NPX * NCG == NT, "shape");
    constexpr int IH = TH + 2, IW = TW + 2, RS = (IW + 3) & ~3;
    extern __shared__ float fsm[];
    float* s_in = fsm;
    float* s_w  = fsm + CI * IH * RS;

    const int tid = threadIdx.x;
    int bid = blockIdx.x;
    const int tx = bid % (W / TW); bid /= (W / TW);
    const int ty = bid % (H / TH); bid /= (H / TH);
    const int b = bid;

    for (int i = tid; i < CI * 9 * CO; i += NT) {
        const int k = i / CO, co = i - k * CO, ci = k / 9, t = k - ci * 9;
        s_w[i] = wgt[(co * CI + ci) * 9 + t];
    }
    const float* inb = in + (size_t)b * CI * H * W;
    const int gy0 = ty * TH - 1, gx0 = tx * TW - 1;
    for (int i = tid; i < CI * IH * IW; i += NT) {
        const int ci = i / (IH * IW);
        int r = i - ci * IH * IW;
        const int y = r / IW, x = r - y * IW;
        const int gy = gy0 + y, gx = gx0 + x;
        float v = 0.f;
        if (gy >= 0 && gy < H && gx >= 0 && gx < W)
            v = inb[(ci * H + gy) * W + gx];
        s_in[(ci * IH + y) * RS + x] = v;
    }
    __syncthreads();

    const int px = tid % NPX, cg = tid / NPX;
    const int py = px / (TW / 8), x0 = (px - py * (TW / 8)) * 8, co0 = cg * 8;
    float acc[8][8];
    #pragma unroll
    for (int i = 0; i < 8; ++i)
        #pragma unroll
        for (int j = 0; j < 8; ++j) acc[i][j] = 0.f;

    #pragma unroll 1
    for (int ci = 0; ci < CI; ++ci)
        #pragma unroll
        for (int dy = 0; dy < 3; ++dy) {
            const float* rp = &s_in[(ci * IH + py + dy) * RS + x0];
            float rr[10];
            const float4 a0 = *reinterpret_cast<const float4*>(rp);
            const float4 a1 = *reinterpret_cast<const float4*>(rp + 4);
            const float2 a2 = *reinterpret_cast<const float2*>(rp + 8);
            rr[0]=a0.x; rr[1]=a0.y; rr[2]=a0.z; rr[3]=a0.w;
            rr[4]=a1.x; rr[5]=a1.y; rr[6]=a1.z; rr[7]=a1.w;
            rr[8]=a2.x; rr[9]=a2.y;
            #pragma unroll
            for (int dx = 0; dx < 3; ++dx) {
                const float* wp = &s_w[(ci * 9 + dy * 3 + dx) * CO + co0];
                const float4 w0 = *reinterpret_cast<const float4*>(wp);
                const float4 w1 = *reinterpret_cast<const float4*>(wp + 4);
                const float wv[8] = {w0.x, w0.y, w0.z, w0.w, w1.x, w1.y, w1.z, w1.w};
                #pragma unroll
                for (int co = 0; co < 8; ++co)
                    #pragma unroll
                    for (int p = 0; p < 8; ++p)
                        acc[co][p] = fmaf(wv[co], rr[p + dx], acc[co][p]);
            }
        }
    float* outb = out + (size_t)b * CO * H * W;
    const int oy = ty * TH + py, ox = tx * TW + x0;
    #pragma unroll
    for (int co = 0; co < 8; ++co) {
        float* op = &outb[((size_t)(co0 + co) * H + oy) * W + ox];
        *reinterpret_cast<float4*>(op)     = make_float4(acc[co][0], acc[co][1], acc[co][2], acc[co][3]);
        *reinterpret_cast<float4*>(op + 4) = make_float4(acc[co][4], acc[co][5], acc[co][6], acc[co][7]);
    }
}

__global__ void zero_stats_kernel() {
    if (threadIdx.x < 2 * COUT) g_stats[threadIdx.x] = 0.f;
}
__global__ void bn_finalize_kernel(const float* __restrict__ gamma,
                                   const float* __restrict__ beta) {
    const int c = threadIdx.x;
    if (c >= COUT) return;
    const float n = (float)B * H * W;
    const float mean = g_stats[c] / n;
    const float var  = g_stats[COUT + c] / n - mean * mean;
    const float sc   = gamma[c] * rsqrtf(var + BN_EPS);
    g_scale[c] = sc;
    g_shift[c] = beta[c] - mean * sc;
}
__global__ void bn_apply_kernel(float* __restrict__ out) {
    const int idx = blockIdx.x * blockDim.x + threadIdx.x;
    const int c = (idx >> 14) & (COUT - 1);
    const float sc = g_scale[c], sh = g_shift[c];
    float4 v = reinterpret_cast<float4*>(out)[idx];
    v.x = fmaf(v.x, sc, sh); v.y = fmaf(v.y, sc, sh);
    v.z = fmaf(v.z, sc, sh); v.w = fmaf(v.w, sc, sh);
    reinterpret_cast<float4*>(out)[idx] = v;
}

extern "C" void kernel_launch(void* const* d_in, const int* in_sizes, int n_in,
                              void* d_out, int out_size) {
    (void)in_sizes; (void)n_in; (void)out_size;
    const float* x     = (const float*)d_in[0];
    const float* w1    = (const float*)d_in[1];
    const float* w2    = (const float*)d_in[2];
    const float* w3    = (const float*)d_in[3];
    const float* gamma = (const float*)d_in[4];
    const float* beta  = (const float*)d_in[5];
    float* out = (float*)d_out;

    float *h1, *h2;
    cudaGetSymbolAddress((void**)&h1, g_h1);
    cudaGetSymbolAddress((void**)&h2, g_h2);

    auto* k1 = conv3x3_tile<CIN0, CMID, 32, 32>;
    auto* k2 = conv3x3_tile<CMID, CMID, 32, 32>;
    constexpr int SM1 = (CIN0 * 34 * 36 + CIN0 * 9 * CMID) * 4;
    constexpr int SM2 = (CMID * 34 * 36 + CMID * 9 * CMID) * 4;
    cudaFuncSetAttribute(k1, cudaFuncAttributeMaxDynamicSharedMemorySize, SM1);
    cudaFuncSetAttribute(k2, cudaFuncAttributeMaxDynamicSharedMemorySize, SM2);
    cudaFuncSetAttribute(conv3_mma, cudaFuncAttributeMaxDynamicSharedMemorySize, SMEM3);

    zero_stats_kernel<<<1, 128>>>();
    k1<<<B * (H / 32) * (W / 32), 256, SM1>>>(x, w1, h1);
    k2<<<B * (H / 32) * (W / 32), 256, SM2>>>(h1, w2, h2);
    conv3_mma<<<B * 32 * 2, 256, SMEM3>>>(h2, w3, out);
    bn_finalize_kernel<<<1, 64>>>(gamma, beta);
    bn_apply_kernel<<<(B * COUT * H * W / 4) / 256, 256>>>(out);
}

// round 7
// speedup vs baseline: 1.6244x; 1.0378x over previous
#include <cuda_runtime.h>
#include <cuda_bf16.h>
#include <cstdint>

static constexpr int B = 16, H = 256, W = 256;
static constexpr int CIN0 = 3, CMID = 16, COUT = 64;
static constexpr float BN_EPS = 1e-5f;

__device__ float g_h1[(size_t)B * CMID * H * W];
__device__ float g_h2[(size_t)B * CMID * H * W];
__device__ float g_stats[2 * COUT];
__device__ float g_scale[COUT];
__device__ float g_shift[COUT];

// ---- smem asm helpers ------------------------------------------------------
__device__ __forceinline__ uint32_t smem_u32(const void* p) {
    uint32_t a;
    asm("{ .reg .u64 t; cvta.to.shared.u64 t, %1; cvt.u32.u64 %0, t; }"
        : "=r"(a) : "l"(p));
    return a;
}
__device__ __forceinline__ void sts64(uint32_t a, uint32_t x, uint32_t y) {
    asm volatile("st.shared.v2.u32 [%0], {%1,%2};" :: "r"(a), "r"(x), "r"(y));
}
__device__ __forceinline__ void sts16(uint32_t a, uint16_t v) {
    asm volatile("st.shared.u16 [%0], %1;" :: "r"(a), "h"(v));
}
__device__ __forceinline__ uint32_t lds32(uint32_t a) {
    uint32_t v;
    asm volatile("ld.shared.b32 %0, [%1];" : "=r"(v) : "r"(a));
    return v;
}
// baseline-PTX bf16 tensor-core mma (sm_80+)
__device__ __forceinline__ void mma_bf16(float d[4], const uint32_t a[4],
                                         const uint32_t b[2]) {
    asm volatile(
        "mma.sync.aligned.m16n8k16.row.col.f32.bf16.bf16.f32 "
        "{%0,%1,%2,%3},{%4,%5,%6,%7},{%8,%9},{%0,%1,%2,%3};"
        : "+f"(d[0]), "+f"(d[1]), "+f"(d[2]), "+f"(d[3])
        : "r"(a[0]), "r"(a[1]), "r"(a[2]), "r"(a[3]), "r"(b[0]), "r"(b[1]));
}

// ---- tensor-core 3x3 conv (16 in-channels), split-bf16 3-term --------------
// A tile per input row: [128 px][K=48], stride 56 bf16 (112 B). Ring of 4
// rows, hi & lo halves. B tile per dy: [CO co][48], same stride, hi & lo.
static constexpr int ASLOT = 28672;             // hi(14336) + lo(14336)
static constexpr int ALO   = 14336;
static constexpr int BBASE = 4 * ASLOT;         // 114688
static constexpr int NY    = 8;
static constexpr int NT    = 512;

__device__ __forceinline__ void stage_row(uint32_t s32, const float* in,
                                          int b, int yin, int x0, int tid) {
    const uint32_t Ah = s32 + (uint32_t)(yin & 3) * ASLOT;
    for (int it = tid; it < 520; it += NT) {
        const int cig = it / 130, xl = it - cig * 130, xin = x0 - 1 + xl;
        uint32_t hb[4], lb[4];
        #pragma unroll
        for (int j = 0; j < 4; ++j) {
            const int ci = cig * 4 + j;
            float v = (xin >= 0 && xin < W)
                    ? in[(((size_t)b * CMID + ci) * H + yin) * W + xin] : 0.f;
            __nv_bfloat16 h = __float2bfloat16_rn(v);
            __nv_bfloat16 l = __float2bfloat16_rn(v - __bfloat162float(h));
            hb[j] = __bfloat16_as_ushort(h);
            lb[j] = __bfloat16_as_ushort(l);
        }
        const uint32_t h0 = hb[0] | (hb[1] << 16), h1 = hb[2] | (hb[3] << 16);
        const uint32_t l0 = lb[0] | (lb[1] << 16), l1 = lb[2] | (lb[3] << 16);
        #pragma unroll
        for (int dx = 0; dx < 3; ++dx) {
            const int r = xl - dx;
            if (r < 0 || r >= 128) continue;
            const uint32_t off = (uint32_t)(r * 112 + (dx * 16 + cig * 4) * 2);
            sts64(Ah + off, h0, h1);
            sts64(Ah + ALO + off, l0, l1);
        }
    }
}

// CO: out channels. Warp grid WM x WN; per-warp fragment grid MF x NF.
// WM*MF*16 == 128, WN*NF*8 == CO, WM*WN == 16 (512 threads).
template <int CO, int WM, int WN, int MF, int NF, bool STATS>
__global__ void __launch_bounds__(NT, 1)
conv_mma(const float* __restrict__ in, const float* __restrict__ wgt,
         float* __restrict__ out) {
    constexpr int BLO  = CO * 112;
    constexpr int BDY  = 2 * BLO;
    constexpr int SOFF = BBASE + 3 * BDY;

    extern __shared__ char sm[];
    const uint32_t s32 = smem_u32(sm);
    float* sstats = (float*)(sm + SOFF);
    const int tid = threadIdx.x, wid = tid >> 5, lid = tid & 31;
    const int g = lid >> 2, tig = lid & 3;
    int bid = blockIdx.x;
    const int xs = bid & 1, ys = (bid >> 1) & 31, b = bid >> 6;
    const int x0 = xs * 128, y0 = ys * NY;

    if (STATS && tid < 128) sstats[tid] = 0.f;
    for (int i = tid; i < CO * CMID * 9; i += NT) {      // weights -> B tiles
        const int dx = i % 3; int t = i / 3;
        const int dy = t % 3; t /= 3;
        const int ci = t & 15, co = t >> 4;
        const float v = wgt[((co * CMID + ci) * 3 + dy) * 3 + dx];
        __nv_bfloat16 h = __float2bfloat16_rn(v);
        __nv_bfloat16 l = __float2bfloat16_rn(v - __bfloat162float(h));
        const uint32_t a = s32 + BBASE + dy * BDY + co * 112 + (dx * 16 + ci) * 2;
        sts16(a, (uint16_t)__bfloat16_as_ushort(h));
        sts16(a + BLO, (uint16_t)__bfloat16_as_ushort(l));
    }
    if (y0 > 0) stage_row(s32, in, b, y0 - 1, x0, tid);
    stage_row(s32, in, b, y0, x0, tid);

    const int wm = wid % WM, wn = wid / WM;
    float sacc[NF][2] = {}, qacc[NF][2] = {};

    for (int i = 0; i < NY; ++i) {
        const int y = y0 + i;
        if (y + 1 < H) stage_row(s32, in, b, y + 1, x0, tid);
        __syncthreads();

        float acc[MF][NF][4];
        #pragma unroll
        for (int mf = 0; mf < MF; ++mf)
            #pragma unroll
            for (int nf = 0; nf < NF; ++nf)
                #pragma unroll
                for (int r = 0; r < 4; ++r) acc[mf][nf][r] = 0.f;

        #pragma unroll
        for (int dy = 0; dy < 3; ++dy) {
            const int yin = y - 1 + dy;
            if (yin < 0 || yin >= H) continue;
            const uint32_t A0 = s32 + (uint32_t)(yin & 3) * ASLOT;
            const uint32_t B0 = s32 + BBASE + dy * BDY;
            #pragma unroll
            for (int ks = 0; ks < 3; ++ks) {
                uint32_t ah[MF][4], al[MF][4], bh[NF][2], bl[NF][2];
                #pragma unroll
                for (int mf = 0; mf < MF; ++mf) {
                    const uint32_t r0 = A0 +
                        (uint32_t)((wm * (MF * 16) + mf * 16 + g) * 112 +
                                   ks * 32 + tig * 4);
                    const uint32_t r1 = r0 + 8 * 112;
                    ah[mf][0] = lds32(r0);        ah[mf][1] = lds32(r1);
                    ah[mf][2] = lds32(r0 + 16);   ah[mf][3] = lds32(r1 + 16);
                    al[mf][0] = lds32(r0 + ALO);  al[mf][1] = lds32(r1 + ALO);
                    al[mf][2] = lds32(r0 + ALO + 16);
                    al[mf][3] = lds32(r1 + ALO + 16);
                }
                #pragma unroll
                for (int nf = 0; nf < NF; ++nf) {
                    const uint32_t c0 = B0 +
                        (uint32_t)((wn * (NF * 8) + nf * 8 + g) * 112 +
                                   ks * 32 + tig * 4);
                    bh[nf][0] = lds32(c0);        bh[nf][1] = lds32(c0 + 16);
                    bl[nf][0] = lds32(c0 + BLO);  bl[nf][1] = lds32(c0 + BLO + 16);
                }
                #pragma unroll
                for (int mf = 0; mf < MF; ++mf)
                    #pragma unroll
                    for (int nf = 0; nf < NF; ++nf) {
                        mma_bf16(acc[mf][nf], ah[mf], bh[nf]);
                        mma_bf16(acc[mf][nf], ah[mf], bl[nf]);
                        mma_bf16(acc[mf][nf], al[mf], bh[nf]);
                    }
            }
        }

        #pragma unroll
        for (int mf = 0; mf < MF; ++mf) {
            const int x = x0 + wm * (MF * 16) + mf * 16 + g;
            #pragma unroll
            for (int nf = 0; nf < NF; ++nf) {
                const int co = wn * (NF * 8) + nf * 8 + tig * 2;
                float* p0 = out + (((size_t)b * CO + co) * H + y) * W + x;
                float* p1 = p0 + (size_t)H * W;
                const float v0 = acc[mf][nf][0], v1 = acc[mf][nf][1];
                const float v2 = acc[mf][nf][2], v3 = acc[mf][nf][3];
                p0[0] = v0; p1[0] = v1; p0[8] = v2; p1[8] = v3;
                if (STATS) {
                    sacc[nf][0] += v0 + v2;
                    sacc[nf][1] += v1 + v3;
                    qacc[nf][0] = fmaf(v0, v0, fmaf(v2, v2, qacc[nf][0]));
                    qacc[nf][1] = fmaf(v1, v1, fmaf(v3, v3, qacc[nf][1]));
                }
            }
        }
    }

    if (STATS) {
        #pragma unroll
        for (int nf = 0; nf < NF; ++nf)
            #pragma unroll
            for (int j = 0; j < 2; ++j) {
                float s = sacc[nf][j], q = qacc[nf][j];
                #pragma unroll
                for (int o = 4; o < 32; o <<= 1) {   // reduce over g
                    s += __shfl_xor_sync(0xffffffffu, s, o);
                    q += __shfl_xor_sync(0xffffffffu, q, o);
                }
                if (g == 0) {
                    const int c = wn * (NF * 8) + nf * 8 + tig * 2 + j;
                    atomicAdd(&sstats[c], s);
                    atomicAdd(&sstats[COUT + c], q);
                }
            }
        __syncthreads();
        if (tid < 128) atomicAdd(&g_stats[tid], sstats[tid]);
    }
}

// ---- scalar tiled conv (conv1 only) ----------------------------------------
template <int CI, int CO, int TH, int TW>
__global__ void __launch_bounds__(256, 2)
conv3x3_tile(const float* __restrict__ in, const float* __restrict__ wgt,
             float* __restrict__ out) {
    constexpr int NTT = 256, NPX = TH * TW / 8, NCG = CO / 8;
    static_assert(NPX * NCG == NTT, "shape");
    constexpr int IH = TH + 2, IW = TW + 2, RS = (IW + 3) & ~3;
    extern __shared__ float fsm[];
    float* s_in = fsm;
    float* s_w  = fsm + CI * IH * RS;

    const int tid = threadIdx.x;
    int bid = blockIdx.x;
    const int tx = bid % (W / TW); bid /= (W / TW);
    const int ty = bid % (H / TH); bid /= (H / TH);
    const int b = bid;

    for (int i = tid; i < CI * 9 * CO; i += NTT) {
        const int k = i / CO, co = i - k * CO, ci = k / 9, t = k - ci * 9;
        s_w[i] = wgt[(co * CI + ci) * 9 + t];
    }
    const float* inb = in + (size_t)b * CI * H * W;
    const int gy0 = ty * TH - 1, gx0 = tx * TW - 1;
    for (int i = tid; i < CI * IH * IW; i += NTT) {
        const int ci = i / (IH * IW);
        int r = i - ci * IH * IW;
        const int y = r / IW, x = r - y * IW;
        const int gy = gy0 + y, gx = gx0 + x;
        float v = 0.f;
        if (gy >= 0 && gy < H && gx >= 0 && gx < W)
            v = inb[(ci * H + gy) * W + gx];
        s_in[(ci * IH + y) * RS + x] = v;
    }
    __syncthreads();

    const int px = tid % NPX, cg = tid / NPX;
    const int py = px / (TW / 8), x0 = (px - py * (TW / 8)) * 8, co0 = cg * 8;
    float acc[8][8];
    #pragma unroll
    for (int i = 0; i < 8; ++i)
        #pragma unroll
        for (int j = 0; j < 8; ++j) acc[i][j] = 0.f;

    #pragma unroll 1
    for (int ci = 0; ci < CI; ++ci)
        #pragma unroll
        for (int dy = 0; dy < 3; ++dy) {
            const float* rp = &s_in[(ci * IH + py + dy) * RS + x0];
            float rr[10];
            const float4 a0 = *reinterpret_cast<const float4*>(rp);
            const float4 a1 = *reinterpret_cast<const float4*>(rp + 4);
            const float2 a2 = *reinterpret_cast<const float2*>(rp + 8);
            rr[0]=a0.x; rr[1]=a0.y; rr[2]=a0.z; rr[3]=a0.w;
            rr[4]=a1.x; rr[5]=a1.y; rr[6]=a1.z; rr[7]=a1.w;
            rr[8]=a2.x; rr[9]=a2.y;
            #pragma unroll
            for (int dx = 0; dx < 3; ++dx) {
                const float* wp = &s_w[(ci * 9 + dy * 3 + dx) * CO + co0];
                const float4 w0 = *reinterpret_cast<const float4*>(wp);
                const float4 w1 = *reinterpret_cast<const float4*>(wp + 4);
                const float wv[8] = {w0.x, w0.y, w0.z, w0.w, w1.x, w1.y, w1.z, w1.w};
                #pragma unroll
                for (int co = 0; co < 8; ++co)
                    #pragma unroll
                    for (int p = 0; p < 8; ++p)
                        acc[co][p] = fmaf(wv[co], rr[p + dx], acc[co][p]);
            }
        }
    float* outb = out + (size_t)b * CO * H * W;
    const int oy = ty * TH + py, ox = tx * TW + x0;
    #pragma unroll
    for (int co = 0; co < 8; ++co) {
        float* op = &outb[((size_t)(co0 + co) * H + oy) * W + ox];
        *reinterpret_cast<float4*>(op)     = make_float4(acc[co][0], acc[co][1], acc[co][2], acc[co][3]);
        *reinterpret_cast<float4*>(op + 4) = make_float4(acc[co][4], acc[co][5], acc[co][6], acc[co][7]);
    }
}

__global__ void zero_stats_kernel() {
    if (threadIdx.x < 2 * COUT) g_stats[threadIdx.x] = 0.f;
}
__global__ void bn_finalize_kernel(const float* __restrict__ gamma,
                                   const float* __restrict__ beta) {
    const int c = threadIdx.x;
    if (c >= COUT) return;
    const float n = (float)B * H * W;
    const float mean = g_stats[c] / n;
    const float var  = g_stats[COUT + c] / n - mean * mean;
    const float sc   = gamma[c] * rsqrtf(var + BN_EPS);
    g_scale[c] = sc;
    g_shift[c] = beta[c] - mean * sc;
}
__global__ void bn_apply_kernel(float* __restrict__ out) {
    const int idx = blockIdx.x * blockDim.x + threadIdx.x;
    const int c = (idx >> 14) & (COUT - 1);
    const float sc = g_scale[c], sh = g_shift[c];
    float4 v = reinterpret_cast<float4*>(out)[idx];
    v.x = fmaf(v.x, sc, sh); v.y = fmaf(v.y, sc, sh);
    v.z = fmaf(v.z, sc, sh); v.w = fmaf(v.w, sc, sh);
    reinterpret_cast<float4*>(out)[idx] = v;
}

extern "C" void kernel_launch(void* const* d_in, const int* in_sizes, int n_in,
                              void* d_out, int out_size) {
    (void)in_sizes; (void)n_in; (void)out_size;
    const float* x     = (const float*)d_in[0];
    const float* w1    = (const float*)d_in[1];
    const float* w2    = (const float*)d_in[2];
    const float* w3    = (const float*)d_in[3];
    const float* gamma = (const float*)d_in[4];
    const float* beta  = (const float*)d_in[5];
    float* out = (float*)d_out;

    float *h1, *h2;
    cudaGetSymbolAddress((void**)&h1, g_h1);
    cudaGetSymbolAddress((void**)&h2, g_h2);

    auto* k1 = conv3x3_tile<CIN0, CMID, 32, 32>;
    auto* k2 = conv_mma<16, 8, 2, 1, 1, false>;
    auto* k3 = conv_mma<64, 4, 4, 2, 2, true>;

    constexpr int SM1 = (CIN0 * 34 * 36 + CIN0 * 9 * CMID) * 4;
    constexpr int SM2 = BBASE + 3 * (2 * 16 * 112) + 512;   // 125,952
    constexpr int SM3 = BBASE + 3 * (2 * 64 * 112) + 512;   // 158,208

    cudaFuncSetAttribute(k1, cudaFuncAttributeMaxDynamicSharedMemorySize, SM1);
    cudaFuncSetAttribute(k2, cudaFuncAttributeMaxDynamicSharedMemorySize, SM2);
    cudaFuncSetAttribute(k3, cudaFuncAttributeMaxDynamicSharedMemorySize, SM3);

    zero_stats_kernel<<<1, 128>>>();
    k1<<<B * (H / 32) * (W / 32), 256, SM1>>>(x, w1, h1);
    k2<<<B * 32 * 2, NT, SM2>>>(h1, w2, h2);
    k3<<<B * 32 * 2, NT, SM3>>>(h2, w3, out);
    bn_finalize_kernel<<<1, 64>>>(gamma, beta);
    bn_apply_kernel<<<(B * COUT * H * W / 4) / 256, 256>>>(out);
}

// round 8
// speedup vs baseline: 1.6573x; 1.0202x over previous
#include <cuda_runtime.h>
#include <cuda_bf16.h>
#include <cstdint>

static constexpr int B = 16, H = 256, W = 256;
static constexpr int CIN0 = 3, CMID = 16, COUT = 64;
static constexpr float BN_EPS = 1e-5f;

// h1/h2 stored pre-split: (bf16_hi << 16) | bf16_lo per element
__device__ uint32_t g_h1[(size_t)B * CMID * H * W];
__device__ uint32_t g_h2[(size_t)B * CMID * H * W];
__device__ float g_stats[2 * COUT];
__device__ float g_scale[COUT];
__device__ float g_shift[COUT];

// ---- helpers ---------------------------------------------------------------
__device__ __forceinline__ uint32_t smem_u32(const void* p) {
    uint32_t a;
    asm("{ .reg .u64 t; cvta.to.shared.u64 t, %1; cvt.u32.u64 %0, t; }"
        : "=r"(a) : "l"(p));
    return a;
}
__device__ __forceinline__ void sts64(uint32_t a, uint32_t x, uint32_t y) {
    asm volatile("st.shared.v2.u32 [%0], {%1,%2};" :: "r"(a), "r"(x), "r"(y));
}
__device__ __forceinline__ void sts16(uint32_t a, uint16_t v) {
    asm volatile("st.shared.u16 [%0], %1;" :: "r"(a), "h"(v));
}
__device__ __forceinline__ uint32_t lds32(uint32_t a) {
    uint32_t v;
    asm volatile("ld.shared.b32 %0, [%1];" : "=r"(v) : "r"(a));
    return v;
}
__device__ __forceinline__ uint32_t packhl(float v) {
    __nv_bfloat16 h = __float2bfloat16_rn(v);
    float lo = v - __bfloat162float(h);
    __nv_bfloat16 l = __float2bfloat16_rn(lo);
    return ((uint32_t)__bfloat16_as_ushort(h) << 16) |
           (uint32_t)__bfloat16_as_ushort(l);
}
// baseline-PTX bf16 tensor-core mma (sm_80+)
__device__ __forceinline__ void mma_bf16(float d[4], const uint32_t a[4],
                                         const uint32_t b[2]) {
    asm volatile(
        "mma.sync.aligned.m16n8k16.row.col.f32.bf16.bf16.f32 "
        "{%0,%1,%2,%3},{%4,%5,%6,%7},{%8,%9},{%0,%1,%2,%3};"
        : "+f"(d[0]), "+f"(d[1]), "+f"(d[2]), "+f"(d[3])
        : "r"(a[0]), "r"(a[1]), "r"(a[2]), "r"(a[3]), "r"(b[0]), "r"(b[1]));
}

// ---- tensor-core 3x3 conv (16 in-ch), split-bf16 3-term --------------------
// A tile per input row: [128 px][K=48], stride 112 B; ring of 4 rows, hi+lo.
// B per dy: [CO][48], hi+lo. Inputs arrive pre-split packed (hi<<16|lo).
static constexpr int ASLOT = 28672;             // hi(14336) + lo(14336)
static constexpr int ALO   = 14336;
static constexpr int BBASE = 4 * ASLOT;         // 114688
static constexpr int NY    = 8;
static constexpr int NT    = 512;

__device__ __forceinline__ void stage_row(uint32_t s32, const uint32_t* in,
                                          int b, int yin, int x0, int tid) {
    const uint32_t Ah = s32 + (uint32_t)(yin & 3) * ASLOT;
    for (int it = tid; it < 520; it += NT) {
        const int cig = it / 130, xl = it - cig * 130, xin = x0 - 1 + xl;
        uint32_t v0 = 0, v1 = 0, v2 = 0, v3 = 0;
        if (xin >= 0 && xin < W) {
            const uint32_t* p =
                in + (((size_t)b * CMID + cig * 4) * H + yin) * W + xin;
            const size_t st = (size_t)H * W;
            v0 = p[0]; v1 = p[st]; v2 = p[2 * st]; v3 = p[3 * st];
        }
        const uint32_t h0 = __byte_perm(v0, v1, 0x7632);
        const uint32_t h1 = __byte_perm(v2, v3, 0x7632);
        const uint32_t l0 = __byte_perm(v0, v1, 0x5410);
        const uint32_t l1 = __byte_perm(v2, v3, 0x5410);
        #pragma unroll
        for (int dx = 0; dx < 3; ++dx) {
            const int r = xl - dx;
            if (r < 0 || r >= 128) continue;
            const uint32_t off = (uint32_t)(r * 112 + (dx * 16 + cig * 4) * 2);
            sts64(Ah + off, h0, h1);
            sts64(Ah + ALO + off, l0, l1);
        }
    }
}

// CO out channels; warp grid WM x WN; per-warp fragments MF x NF.
// WM*MF*16 == 128, WN*NF*8 == CO, WM*WN == 16. OUTF32: fp32 out (else packed).
template <int CO, int WM, int WN, int MF, int NF, bool STATS, bool OUTF32>
__global__ void __launch_bounds__(NT, 1)
conv_mma(const uint32_t* __restrict__ in, const float* __restrict__ wgt,
         void* __restrict__ outv) {
    constexpr int BLO  = CO * 112;
    constexpr int BDY  = 2 * BLO;
    constexpr int SOFF = BBASE + 3 * BDY;

    extern __shared__ char sm[];
    const uint32_t s32 = smem_u32(sm);
    float* sstats = (float*)(sm + SOFF);
    const int tid = threadIdx.x, wid = tid >> 5, lid = tid & 31;
    const int g = lid >> 2, tig = lid & 3;
    int bid = blockIdx.x;
    const int xs = bid & 1, ys = (bid >> 1) & 31, b = bid >> 6;
    const int x0 = xs * 128, y0 = ys * NY;

    if (STATS && tid < 128) sstats[tid] = 0.f;
    for (int i = tid; i < CO * CMID * 9; i += NT) {      // weights -> B tiles
        const int dx = i % 3; int t = i / 3;
        const int dy = t % 3; t /= 3;
        const int ci = t & 15, co = t >> 4;
        const float v = wgt[((co * CMID + ci) * 3 + dy) * 3 + dx];
        __nv_bfloat16 h = __float2bfloat16_rn(v);
        __nv_bfloat16 l = __float2bfloat16_rn(v - __bfloat162float(h));
        const uint32_t a = s32 + BBASE + dy * BDY + co * 112 + (dx * 16 + ci) * 2;
        sts16(a, (uint16_t)__bfloat16_as_ushort(h));
        sts16(a + BLO, (uint16_t)__bfloat16_as_ushort(l));
    }
    // prologue: rows y0-1, y0, y0+1 staged before first compute
    if (y0 > 0) stage_row(s32, in, b, y0 - 1, x0, tid);
    stage_row(s32, in, b, y0, x0, tid);
    stage_row(s32, in, b, y0 + 1, x0, tid);
    __syncthreads();

    const int wm = wid % WM, wn = wid / WM;
    float sacc[NF][2] = {}, qacc[NF][2] = {};

    for (int i = 0; i < NY; ++i) {
        const int y = y0 + i;
        // prefetch distance 2: slot (y+2)&3 disjoint from the 3 slots read now
        if (y + 2 < H) stage_row(s32, in, b, y + 2, x0, tid);

        float acc[MF][NF][4];
        #pragma unroll
        for (int mf = 0; mf < MF; ++mf)
            #pragma unroll
            for (int nf = 0; nf < NF; ++nf)
                #pragma unroll
                for (int r = 0; r < 4; ++r) acc[mf][nf][r] = 0.f;

        #pragma unroll
        for (int dy = 0; dy < 3; ++dy) {
            const int yin = y - 1 + dy;
            if (yin < 0 || yin >= H) continue;
            const uint32_t A0 = s32 + (uint32_t)(yin & 3) * ASLOT;
            const uint32_t B0 = s32 + BBASE + dy * BDY;
            #pragma unroll
            for (int ks = 0; ks < 3; ++ks) {
                uint32_t ah[MF][4], al[MF][4], bh[NF][2], bl[NF][2];
                #pragma unroll
                for (int mf = 0; mf < MF; ++mf) {
                    const uint32_t r0 = A0 +
                        (uint32_t)((wm * (MF * 16) + mf * 16 + g) * 112 +
                                   ks * 32 + tig * 4);
                    const uint32_t r1 = r0 + 8 * 112;
                    ah[mf][0] = lds32(r0);        ah[mf][1] = lds32(r1);
                    ah[mf][2] = lds32(r0 + 16);   ah[mf][3] = lds32(r1 + 16);
                    al[mf][0] = lds32(r0 + ALO);  al[mf][1] = lds32(r1 + ALO);
                    al[mf][2] = lds32(r0 + ALO + 16);
                    al[mf][3] = lds32(r1 + ALO + 16);
                }
                #pragma unroll
                for (int nf = 0; nf < NF; ++nf) {
                    const uint32_t c0 = B0 +
                        (uint32_t)((wn * (NF * 8) + nf * 8 + g) * 112 +
                                   ks * 32 + tig * 4);
                    bh[nf][0] = lds32(c0);        bh[nf][1] = lds32(c0 + 16);
                    bl[nf][0] = lds32(c0 + BLO);  bl[nf][1] = lds32(c0 + BLO + 16);
                }
                #pragma unroll
                for (int mf = 0; mf < MF; ++mf)
                    #pragma unroll
                    for (int nf = 0; nf < NF; ++nf) {
                        mma_bf16(acc[mf][nf], ah[mf], bh[nf]);
                        mma_bf16(acc[mf][nf], ah[mf], bl[nf]);
                        mma_bf16(acc[mf][nf], al[mf], bh[nf]);
                    }
            }
        }

        #pragma unroll
        for (int mf = 0; mf < MF; ++mf) {
            const int x = x0 + wm * (MF * 16) + mf * 16 + g;
            #pragma unroll
            for (int nf = 0; nf < NF; ++nf) {
                const int co = wn * (NF * 8) + nf * 8 + tig * 2;
                const size_t base = (((size_t)b * CO + co) * H + y) * W + x;
                const float v0 = acc[mf][nf][0], v1 = acc[mf][nf][1];
                const float v2 = acc[mf][nf][2], v3 = acc[mf][nf][3];
                if (OUTF32) {
                    float* p0 = (float*)outv + base;
                    float* p1 = p0 + (size_t)H * W;
                    p0[0] = v0; p1[0] = v1; p0[8] = v2; p1[8] = v3;
                } else {
                    uint32_t* p0 = (uint32_t*)outv + base;
                    uint32_t* p1 = p0 + (size_t)H * W;
                    p0[0] = packhl(v0); p1[0] = packhl(v1);
                    p0[8] = packhl(v2); p1[8] = packhl(v3);
                }
                if (STATS) {
                    sacc[nf][0] += v0 + v2;
                    sacc[nf][1] += v1 + v3;
                    qacc[nf][0] = fmaf(v0, v0, fmaf(v2, v2, qacc[nf][0]));
                    qacc[nf][1] = fmaf(v1, v1, fmaf(v3, v3, qacc[nf][1]));
                }
            }
        }
        __syncthreads();
    }

    if (STATS) {
        #pragma unroll
        for (int nf = 0; nf < NF; ++nf)
            #pragma unroll
            for (int j = 0; j < 2; ++j) {
                float s = sacc[nf][j], q = qacc[nf][j];
                #pragma unroll
                for (int o = 4; o < 32; o <<= 1) {
                    s += __shfl_xor_sync(0xffffffffu, s, o);
                    q += __shfl_xor_sync(0xffffffffu, q, o);
                }
                if (g == 0) {
                    const int c = wn * (NF * 8) + nf * 8 + tig * 2 + j;
                    atomicAdd(&sstats[c], s);
                    atomicAdd(&sstats[COUT + c], q);
                }
            }
        __syncthreads();
        if (tid < 128) atomicAdd(&g_stats[tid], sstats[tid]);
    }
}

// ---- scalar tiled conv (conv1), packed hi/lo output ------------------------
template <int CI, int CO, int TH, int TW>
__global__ void __launch_bounds__(256, 2)
conv3x3_tile(const float* __restrict__ in, const float* __restrict__ wgt,
             uint32_t* __restrict__ out) {
    constexpr int NTT = 256, NPX = TH * TW / 8, NCG = CO / 8;
    static_assert(NPX * NCG == NTT, "shape");
    constexpr int IH = TH + 2, IW = TW + 2, RS = (IW + 3) & ~3;
    extern __shared__ float fsm[];
    float* s_in = fsm;
    float* s_w  = fsm + CI * IH * RS;

    const int tid = threadIdx.x;
    int bid = blockIdx.x;
    const int tx = bid % (W / TW); bid /= (W / TW);
    const int ty = bid % (H / TH); bid /= (H / TH);
    const int b = bid;

    for (int i = tid; i < CI * 9 * CO; i += NTT) {
        const int k = i / CO, co = i - k * CO, ci = k / 9, t = k - ci * 9;
        s_w[i] = wgt[(co * CI + ci) * 9 + t];
    }
    const float* inb = in + (size_t)b * CI * H * W;
    const int gy0 = ty * TH - 1, gx0 = tx * TW - 1;
    for (int i = tid; i < CI * IH * IW; i += NTT) {
        const int ci = i / (IH * IW);
        int r = i - ci * IH * IW;
        const int y = r / IW, x = r - y * IW;
        const int gy = gy0 + y, gx = gx0 + x;
        float v = 0.f;
        if (gy >= 0 && gy < H && gx >= 0 && gx < W)
            v = inb[(ci * H + gy) * W + gx];
        s_in[(ci * IH + y) * RS + x] = v;
    }
    __syncthreads();

    const int px = tid % NPX, cg = tid / NPX;
    const int py = px / (TW / 8), x0 = (px - py * (TW / 8)) * 8, co0 = cg * 8;
    float acc[8][8];
    #pragma unroll
    for (int i = 0; i < 8; ++i)
        #pragma unroll
        for (int j = 0; j < 8; ++j) acc[i][j] = 0.f;

    #pragma unroll 1
    for (int ci = 0; ci < CI; ++ci)
        #pragma unroll
        for (int dy = 0; dy < 3; ++dy) {
            const float* rp = &s_in[(ci * IH + py + dy) * RS + x0];
            float rr[10];
            const float4 a0 = *reinterpret_cast<const float4*>(rp);
            const float4 a1 = *reinterpret_cast<const float4*>(rp + 4);
            const float2 a2 = *reinterpret_cast<const float2*>(rp + 8);
            rr[0]=a0.x; rr[1]=a0.y; rr[2]=a0.z; rr[3]=a0.w;
            rr[4]=a1.x; rr[5]=a1.y; rr[6]=a1.z; rr[7]=a1.w;
            rr[8]=a2.x; rr[9]=a2.y;
            #pragma unroll
            for (int dx = 0; dx < 3; ++dx) {
                const float* wp = &s_w[(ci * 9 + dy * 3 + dx) * CO + co0];
                const float4 w0 = *reinterpret_cast<const float4*>(wp);
                const float4 w1 = *reinterpret_cast<const float4*>(wp + 4);
                const float wv[8] = {w0.x, w0.y, w0.z, w0.w, w1.x, w1.y, w1.z, w1.w};
                #pragma unroll
                for (int co = 0; co < 8; ++co)
                    #pragma unroll
                    for (int p = 0; p < 8; ++p)
                        acc[co][p] = fmaf(wv[co], rr[p + dx], acc[co][p]);
            }
        }
    uint32_t* outb = out + (size_t)b * CO * H * W;
    const int oy = ty * TH + py, ox = tx * TW + x0;
    #pragma unroll
    for (int co = 0; co < 8; ++co) {
        uint32_t* op = &outb[((size_t)(co0 + co) * H + oy) * W + ox];
        uint4 u0, u1;
        u0.x = packhl(acc[co][0]); u0.y = packhl(acc[co][1]);
        u0.z = packhl(acc[co][2]); u0.w = packhl(acc[co][3]);
        u1.x = packhl(acc[co][4]); u1.y = packhl(acc[co][5]);
        u1.z = packhl(acc[co][6]); u1.w = packhl(acc[co][7]);
        *reinterpret_cast<uint4*>(op)     = u0;
        *reinterpret_cast<uint4*>(op + 4) = u1;
    }
}

__global__ void zero_stats_kernel() {
    if (threadIdx.x < 2 * COUT) g_stats[threadIdx.x] = 0.f;
}
__global__ void bn_finalize_kernel(const float* __restrict__ gamma,
                                   const float* __restrict__ beta) {
    const int c = threadIdx.x;
    if (c >= COUT) return;
    const float n = (float)B * H * W;
    const float mean = g_stats[c] / n;
    const float var  = g_stats[COUT + c] / n - mean * mean;
    const float sc   = gamma[c] * rsqrtf(var + BN_EPS);
    g_scale[c] = sc;
    g_shift[c] = beta[c] - mean * sc;
}
__global__ void bn_apply_kernel(float* __restrict__ out) {
    const int idx = blockIdx.x * blockDim.x + threadIdx.x;
    const int c = (idx >> 14) & (COUT - 1);
    const float sc = g_scale[c], sh = g_shift[c];
    float4 v = reinterpret_cast<float4*>(out)[idx];
    v.x = fmaf(v.x, sc, sh); v.y = fmaf(v.y, sc, sh);
    v.z = fmaf(v.z, sc, sh); v.w = fmaf(v.w, sc, sh);
    reinterpret_cast<float4*>(out)[idx] = v;
}

extern "C" void kernel_launch(void* const* d_in, const int* in_sizes, int n_in,
                              void* d_out, int out_size) {
    (void)in_sizes; (void)n_in; (void)out_size;
    const float* x     = (const float*)d_in[0];
    const float* w1    = (const float*)d_in[1];
    const float* w2    = (const float*)d_in[2];
    const float* w3    = (const float*)d_in[3];
    const float* gamma = (const float*)d_in[4];
    const float* beta  = (const float*)d_in[5];
    float* out = (float*)d_out;

    uint32_t *h1, *h2;
    cudaGetSymbolAddress((void**)&h1, g_h1);
    cudaGetSymbolAddress((void**)&h2, g_h2);

    auto* k1 = conv3x3_tile<CIN0, CMID, 32, 32>;
    auto* k2 = conv_mma<16, 8, 2, 1, 1, false, false>;   // h1 -> packed h2
    auto* k3 = conv_mma<64, 4, 4, 2, 2, true,  true>;    // h2 -> fp32 out

    constexpr int SM1 = (CIN0 * 34 * 36 + CIN0 * 9 * CMID) * 4;
    constexpr int SM2 = BBASE + 3 * (2 * 16 * 112) + 512;   // 125,952
    constexpr int SM3 = BBASE + 3 * (2 * 64 * 112) + 512;   // 158,208

    cudaFuncSetAttribute(k1, cudaFuncAttributeMaxDynamicSharedMemorySize, SM1);
    cudaFuncSetAttribute(k2, cudaFuncAttributeMaxDynamicSharedMemorySize, SM2);
    cudaFuncSetAttribute(k3, cudaFuncAttributeMaxDynamicSharedMemorySize, SM3);

    zero_stats_kernel<<<1, 128>>>();
    k1<<<B * (H / 32) * (W / 32), 256, SM1>>>(x, w1, h1);
    k2<<<B * 32 * 2, NT, SM2>>>(h1, w2, h2);
    k3<<<B * 32 * 2, NT, SM3>>>(h2, w3, out);
    bn_finalize_kernel<<<1, 64>>>(gamma, beta);
    bn_apply_kernel<<<(B * COUT * H * W / 4) / 256, 256>>>(out);
}

// round 9
// speedup vs baseline: 1.9435x; 1.1727x over previous
#include <cuda_runtime.h>
#include <cuda_bf16.h>
#include <cstdint>

static constexpr int B = 16, H = 256, W = 256;
static constexpr int CIN0 = 3, CMID = 16, COUT = 64;
static constexpr float BN_EPS = 1e-5f;

// h1/h2 stored pre-split: (bf16_hi << 16) | bf16_lo per element
__device__ uint32_t g_h1[(size_t)B * CMID * H * W];
__device__ uint32_t g_h2[(size_t)B * CMID * H * W];
__device__ float g_stats[2 * COUT];
__device__ float g_scale[COUT];
__device__ float g_shift[COUT];

// ---- helpers ---------------------------------------------------------------
__device__ __forceinline__ uint32_t smem_u32(const void* p) {
    uint32_t a;
    asm("{ .reg .u64 t; cvta.to.shared.u64 t, %1; cvt.u32.u64 %0, t; }"
        : "=r"(a) : "l"(p));
    return a;
}
__device__ __forceinline__ void sts64(uint32_t a, uint32_t x, uint32_t y) {
    asm volatile("st.shared.v2.u32 [%0], {%1,%2};" :: "r"(a), "r"(x), "r"(y));
}
__device__ __forceinline__ void sts16(uint32_t a, uint16_t v) {
    asm volatile("st.shared.u16 [%0], %1;" :: "r"(a), "h"(v));
}
__device__ __forceinline__ uint32_t lds32(uint32_t a) {
    uint32_t v;
    asm volatile("ld.shared.b32 %0, [%1];" : "=r"(v) : "r"(a));
    return v;
}
__device__ __forceinline__ uint32_t packhl(float v) {
    __nv_bfloat16 h = __float2bfloat16_rn(v);
    float lo = v - __bfloat162float(h);
    __nv_bfloat16 l = __float2bfloat16_rn(lo);
    return ((uint32_t)__bfloat16_as_ushort(h) << 16) |
           (uint32_t)__bfloat16_as_ushort(l);
}
// baseline-PTX bf16 tensor-core mma (sm_80+)
__device__ __forceinline__ void mma_bf16(float d[4], const uint32_t a[4],
                                         const uint32_t b[2]) {
    asm volatile(
        "mma.sync.aligned.m16n8k16.row.col.f32.bf16.bf16.f32 "
        "{%0,%1,%2,%3},{%4,%5,%6,%7},{%8,%9},{%0,%1,%2,%3};"
        : "+f"(d[0]), "+f"(d[1]), "+f"(d[2]), "+f"(d[3])
        : "r"(a[0]), "r"(a[1]), "r"(a[2]), "r"(a[3]), "r"(b[0]), "r"(b[1]));
}

// ---- tensor-core 3x3 conv (16 in-ch), split-bf16 3-term --------------------
// Tile: 64 px (M) x CO. A per input row: [64 px][K=48], stride 112 B, hi+lo;
// ring of 4 rows. B per dy: [CO][48], hi+lo. 256 threads, 2 blocks/SM.
static constexpr int ALO   = 7168;              // lo half offset within slot
static constexpr int ASLOT = 14336;             // hi + lo per row
static constexpr int BBASE = 4 * ASLOT;         // 57344
static constexpr int NY    = 8;
static constexpr int NT    = 256;
static constexpr int NITEM = 264;               // 66 x-px * 4 ci-groups

__device__ __forceinline__ void stage_load(const uint32_t* in, int b, int yin,
                                           int x0, int tid, uint32_t v[2][4]) {
    #pragma unroll
    for (int j = 0; j < 2; ++j) {
        v[j][0] = v[j][1] = v[j][2] = v[j][3] = 0;
        const int it = tid + j * NT;
        if (it >= NITEM) continue;
        const int cig = it / 66, xl = it - cig * 66, xin = x0 - 1 + xl;
        if (xin >= 0 && xin < W) {
            const uint32_t* p =
                in + (((size_t)b * CMID + cig * 4) * H + yin) * W + xin;
            const size_t st = (size_t)H * W;
            v[j][0] = p[0]; v[j][1] = p[st];
            v[j][2] = p[2 * st]; v[j][3] = p[3 * st];
        }
    }
}
__device__ __forceinline__ void stage_store(uint32_t s32, int yin, int tid,
                                            const uint32_t v[2][4]) {
    const uint32_t Ah = s32 + (uint32_t)(yin & 3) * ASLOT;
    #pragma unroll
    for (int j = 0; j < 2; ++j) {
        const int it = tid + j * NT;
        if (it >= NITEM) continue;
        const int cig = it / 66, xl = it - cig * 66;
        const uint32_t h0 = __byte_perm(v[j][0], v[j][1], 0x7632);
        const uint32_t h1 = __byte_perm(v[j][2], v[j][3], 0x7632);
        const uint32_t l0 = __byte_perm(v[j][0], v[j][1], 0x5410);
        const uint32_t l1 = __byte_perm(v[j][2], v[j][3], 0x5410);
        #pragma unroll
        for (int dx = 0; dx < 3; ++dx) {
            const int r = xl - dx;
            if (r < 0 || r >= 64) continue;
            const uint32_t off = (uint32_t)(r * 112 + (dx * 16 + cig * 4) * 2);
            sts64(Ah + off, h0, h1);
            sts64(Ah + ALO + off, l0, l1);
        }
    }
}

// Warp grid WM x WN, per-warp fragments MF x NF.
// WM*MF*16 == 64, WN*NF*8 == CO, WM*WN == 8 (256 threads).
template <int CO, int WM, int WN, int MF, int NF, bool STATS, bool OUTF32>
__global__ void __launch_bounds__(NT, 2)
conv_mma(const uint32_t* __restrict__ in, const float* __restrict__ wgt,
         void* __restrict__ outv) {
    static_assert(WM * MF * 16 == 64 && WN * NF * 8 == CO && WM * WN == 8, "");
    constexpr int BLO  = CO * 112;
    constexpr int BDY  = 2 * BLO;
    constexpr int SOFF = BBASE + 3 * BDY;

    extern __shared__ char sm[];
    const uint32_t s32 = smem_u32(sm);
    float* sstats = (float*)(sm + SOFF);
    const int tid = threadIdx.x, wid = tid >> 5, lid = tid & 31;
    const int g = lid >> 2, tig = lid & 3;
    int bid = blockIdx.x;
    const int xs = bid & 3, ys = (bid >> 2) & 31, b = bid >> 7;
    const int x0 = xs * 64, y0 = ys * NY;

    if (STATS && tid < 128) sstats[tid] = 0.f;
    for (int i = tid; i < CO * CMID * 9; i += NT) {      // weights -> B tiles
        const int dx = i % 3; int t = i / 3;
        const int dy = t % 3; t /= 3;
        const int ci = t & 15, co = t >> 4;
        const float v = wgt[((co * CMID + ci) * 3 + dy) * 3 + dx];
        __nv_bfloat16 h = __float2bfloat16_rn(v);
        __nv_bfloat16 l = __float2bfloat16_rn(v - __bfloat162float(h));
        const uint32_t a = s32 + BBASE + dy * BDY + co * 112 + (dx * 16 + ci) * 2;
        sts16(a, (uint16_t)__bfloat16_as_ushort(h));
        sts16(a + BLO, (uint16_t)__bfloat16_as_ushort(l));
    }
    {   // prologue: rows y0-1, y0, y0+1
        uint32_t pv[2][4];
        if (y0 > 0) {
            stage_load(in, b, y0 - 1, x0, tid, pv);
            stage_store(s32, y0 - 1, tid, pv);
        }
        stage_load(in, b, y0, x0, tid, pv);
        stage_store(s32, y0, tid, pv);
        stage_load(in, b, y0 + 1, x0, tid, pv);
        stage_store(s32, y0 + 1, tid, pv);
    }
    __syncthreads();

    const int wm = wid % WM, wn = wid / WM;
    float sacc[NF][2] = {}, qacc[NF][2] = {};

    for (int i = 0; i < NY; ++i) {
        const int y = y0 + i;
        const bool have = (y + 2 < H);
        uint32_t pf[2][4];
        if (have) stage_load(in, b, y + 2, x0, tid, pf);  // LDG early

        float acc[MF][NF][4];
        #pragma unroll
        for (int mf = 0; mf < MF; ++mf)
            #pragma unroll
            for (int nf = 0; nf < NF; ++nf)
                #pragma unroll
                for (int r = 0; r < 4; ++r) acc[mf][nf][r] = 0.f;

        #pragma unroll
        for (int dy = 0; dy < 3; ++dy) {
            const int yin = y - 1 + dy;
            if (yin < 0 || yin >= H) continue;
            const uint32_t A0 = s32 + (uint32_t)(yin & 3) * ASLOT;
            const uint32_t B0 = s32 + BBASE + dy * BDY;
            #pragma unroll
            for (int ks = 0; ks < 3; ++ks) {
                uint32_t ah[MF][4], al[MF][4], bh[NF][2], bl[NF][2];
                #pragma unroll
                for (int mf = 0; mf < MF; ++mf) {
                    const uint32_t r0 = A0 +
                        (uint32_t)((wm * (MF * 16) + mf * 16 + g) * 112 +
                                   ks * 32 + tig * 4);
                    const uint32_t r1 = r0 + 8 * 112;
                    ah[mf][0] = lds32(r0);        ah[mf][1] = lds32(r1);
                    ah[mf][2] = lds32(r0 + 16);   ah[mf][3] = lds32(r1 + 16);
                    al[mf][0] = lds32(r0 + ALO);  al[mf][1] = lds32(r1 + ALO);
                    al[mf][2] = lds32(r0 + ALO + 16);
                    al[mf][3] = lds32(r1 + ALO + 16);
                }
                #pragma unroll
                for (int nf = 0; nf < NF; ++nf) {
                    const uint32_t c0 = B0 +
                        (uint32_t)((wn * (NF * 8) + nf * 8 + g) * 112 +
                                   ks * 32 + tig * 4);
                    bh[nf][0] = lds32(c0);        bh[nf][1] = lds32(c0 + 16);
                    bl[nf][0] = lds32(c0 + BLO);  bl[nf][1] = lds32(c0 + BLO + 16);
                }
                #pragma unroll
                for (int mf = 0; mf < MF; ++mf)
                    #pragma unroll
                    for (int nf = 0; nf < NF; ++nf) {
                        mma_bf16(acc[mf][nf], ah[mf], bh[nf]);
                        mma_bf16(acc[mf][nf], ah[mf], bl[nf]);
                        mma_bf16(acc[mf][nf], al[mf], bh[nf]);
                    }
            }
        }

        #pragma unroll
        for (int mf = 0; mf < MF; ++mf) {
            const int x = x0 + wm * (MF * 16) + mf * 16 + g;
            #pragma unroll
            for (int nf = 0; nf < NF; ++nf) {
                const int co = wn * (NF * 8) + nf * 8 + tig * 2;
                const size_t base = (((size_t)b * CO + co) * H + y) * W + x;
                const float v0 = acc[mf][nf][0], v1 = acc[mf][nf][1];
                const float v2 = acc[mf][nf][2], v3 = acc[mf][nf][3];
                if (OUTF32) {
                    float* p0 = (float*)outv + base;
                    float* p1 = p0 + (size_t)H * W;
                    p0[0] = v0; p1[0] = v1; p0[8] = v2; p1[8] = v3;
                } else {
                    uint32_t* p0 = (uint32_t*)outv + base;
                    uint32_t* p1 = p0 + (size_t)H * W;
                    p0[0] = packhl(v0); p1[0] = packhl(v1);
                    p0[8] = packhl(v2); p1[8] = packhl(v3);
                }
                if (STATS) {
                    sacc[nf][0] += v0 + v2;
                    sacc[nf][1] += v1 + v3;
                    qacc[nf][0] = fmaf(v0, v0, fmaf(v2, v2, qacc[nf][0]));
                    qacc[nf][1] = fmaf(v1, v1, fmaf(v3, v3, qacc[nf][1]));
                }
            }
        }
        if (have) stage_store(s32, y + 2, tid, pf);  // slot (y+2)&3 disjoint
        __syncthreads();
    }

    if (STATS) {
        #pragma unroll
        for (int nf = 0; nf < NF; ++nf)
            #pragma unroll
            for (int j = 0; j < 2; ++j) {
                float s = sacc[nf][j], q = qacc[nf][j];
                #pragma unroll
                for (int o = 4; o < 32; o <<= 1) {
                    s += __shfl_xor_sync(0xffffffffu, s, o);
                    q += __shfl_xor_sync(0xffffffffu, q, o);
                }
                if (g == 0) {
                    const int c = wn * (NF * 8) + nf * 8 + tig * 2 + j;
                    atomicAdd(&sstats[c], s);
                    atomicAdd(&sstats[COUT + c], q);
                }
            }
        __syncthreads();
        if (tid < 128) atomicAdd(&g_stats[tid], sstats[tid]);
    }
}

// ---- scalar tiled conv (conv1), packed hi/lo output ------------------------
template <int CI, int CO, int TH, int TW>
__global__ void __launch_bounds__(256, 2)
conv3x3_tile(const float* __restrict__ in, const float* __restrict__ wgt,
             uint32_t* __restrict__ out) {
    constexpr int NTT = 256, NPX = TH * TW / 8, NCG = CO / 8;
    static_assert(NPX * NCG == NTT, "shape");
    constexpr int IH = TH + 2, IW = TW + 2, RS = (IW + 3) & ~3;
    extern __shared__ float fsm[];
    float* s_in = fsm;
    float* s_w  = fsm + CI * IH * RS;

    const int tid = threadIdx.x;
    int bid = blockIdx.x;
    const int tx = bid % (W / TW); bid /= (W / TW);
    const int ty = bid % (H / TH); bid /= (H / TH);
    const int b = bid;

    for (int i = tid; i < CI * 9 * CO; i += NTT) {
        const int k = i / CO, co = i - k * CO, ci = k / 9, t = k - ci * 9;
        s_w[i] = wgt[(co * CI + ci) * 9 + t];
    }
    const float* inb = in + (size_t)b * CI * H * W;
    const int gy0 = ty * TH - 1, gx0 = tx * TW - 1;
    for (int i = tid; i < CI * IH * IW; i += NTT) {
        const int ci = i / (IH * IW);
        int r = i - ci * IH * IW;
        const int y = r / IW, x = r - y * IW;
        const int gy = gy0 + y, gx = gx0 + x;
        float v = 0.f;
        if (gy >= 0 && gy < H && gx >= 0 && gx < W)
            v = inb[(ci * H + gy) * W + gx];
        s_in[(ci * IH + y) * RS + x] = v;
    }
    __syncthreads();

    const int px = tid % NPX, cg = tid / NPX;
    const int py = px / (TW / 8), x0 = (px - py * (TW / 8)) * 8, co0 = cg * 8;
    float acc[8][8];
    #pragma unroll
    for (int i = 0; i < 8; ++i)
        #pragma unroll
        for (int j = 0; j < 8; ++j) acc[i][j] = 0.f;

    #pragma unroll 1
    for (int ci = 0; ci < CI; ++ci)
        #pragma unroll
        for (int dy = 0; dy < 3; ++dy) {
            const float* rp = &s_in[(ci * IH + py + dy) * RS + x0];
            float rr[10];
            const float4 a0 = *reinterpret_cast<const float4*>(rp);
            const float4 a1 = *reinterpret_cast<const float4*>(rp + 4);
            const float2 a2 = *reinterpret_cast<const float2*>(rp + 8);
            rr[0]=a0.x; rr[1]=a0.y; rr[2]=a0.z; rr[3]=a0.w;
            rr[4]=a1.x; rr[5]=a1.y; rr[6]=a1.z; rr[7]=a1.w;
            rr[8]=a2.x; rr[9]=a2.y;
            #pragma unroll
            for (int dx = 0; dx < 3; ++dx) {
                const float* wp = &s_w[(ci * 9 + dy * 3 + dx) * CO + co0];
                const float4 w0 = *reinterpret_cast<const float4*>(wp);
                const float4 w1 = *reinterpret_cast<const float4*>(wp + 4);
                const float wv[8] = {w0.x, w0.y, w0.z, w0.w, w1.x, w1.y, w1.z, w1.w};
                #pragma unroll
                for (int co = 0; co < 8; ++co)
                    #pragma unroll
                    for (int p = 0; p < 8; ++p)
                        acc[co][p] = fmaf(wv[co], rr[p + dx], acc[co][p]);
            }
        }
    uint32_t* outb = out + (size_t)b * CO * H * W;
    const int oy = ty * TH + py, ox = tx * TW + x0;
    #pragma unroll
    for (int co = 0; co < 8; ++co) {
        uint32_t* op = &outb[((size_t)(co0 + co) * H + oy) * W + ox];
        uint4 u0, u1;
        u0.x = packhl(acc[co][0]); u0.y = packhl(acc[co][1]);
        u0.z = packhl(acc[co][2]); u0.w = packhl(acc[co][3]);
        u1.x = packhl(acc[co][4]); u1.y = packhl(acc[co][5]);
        u1.z = packhl(acc[co][6]); u1.w = packhl(acc[co][7]);
        *reinterpret_cast<uint4*>(op)     = u0;
        *reinterpret_cast<uint4*>(op + 4) = u1;
    }
}

__global__ void zero_stats_kernel() {
    if (threadIdx.x < 2 * COUT) g_stats[threadIdx.x] = 0.f;
}
__global__ void bn_finalize_kernel(const float* __restrict__ gamma,
                                   const float* __restrict__ beta) {
    const int c = threadIdx.x;
    if (c >= COUT) return;
    const float n = (float)B * H * W;
    const float mean = g_stats[c] / n;
    const float var  = g_stats[COUT + c] / n - mean * mean;
    const float sc   = gamma[c] * rsqrtf(var + BN_EPS);
    g_scale[c] = sc;
    g_shift[c] = beta[c] - mean * sc;
}
__global__ void bn_apply_kernel(float* __restrict__ out) {
    const int idx = blockIdx.x * blockDim.x + threadIdx.x;
    const int c = (idx >> 14) & (COUT - 1);
    const float sc = g_scale[c], sh = g_shift[c];
    float4 v = reinterpret_cast<float4*>(out)[idx];
    v.x = fmaf(v.x, sc, sh); v.y = fmaf(v.y, sc, sh);
    v.z = fmaf(v.z, sc, sh); v.w = fmaf(v.w, sc, sh);
    reinterpret_cast<float4*>(out)[idx] = v;
}

extern "C" void kernel_launch(void* const* d_in, const int* in_sizes, int n_in,
                              void* d_out, int out_size) {
    (void)in_sizes; (void)n_in; (void)out_size;
    const float* x     = (const float*)d_in[0];
    const float* w1    = (const float*)d_in[1];
    const float* w2    = (const float*)d_in[2];
    const float* w3    = (const float*)d_in[3];
    const float* gamma = (const float*)d_in[4];
    const float* beta  = (const float*)d_in[5];
    float* out = (float*)d_out;

    uint32_t *h1, *h2;
    cudaGetSymbolAddress((void**)&h1, g_h1);
    cudaGetSymbolAddress((void**)&h2, g_h2);

    auto* k1 = conv3x3_tile<CIN0, CMID, 32, 32>;
    auto* k2 = conv_mma<16, 4, 2, 1, 1, false, false>;   // h1 -> packed h2
    auto* k3 = conv_mma<64, 2, 4, 2, 2, true,  true>;    // h2 -> fp32 out

    constexpr int SM1 = (CIN0 * 34 * 36 + CIN0 * 9 * CMID) * 4;
    constexpr int SM2 = BBASE + 3 * (2 * 16 * 112) + 512;   //  68,608
    constexpr int SM3 = BBASE + 3 * (2 * 64 * 112) + 512;   // 100,864

    cudaFuncSetAttribute(k1, cudaFuncAttributeMaxDynamicSharedMemorySize, SM1);
    cudaFuncSetAttribute(k2, cudaFuncAttributeMaxDynamicSharedMemorySize, SM2);
    cudaFuncSetAttribute(k3, cudaFuncAttributeMaxDynamicSharedMemorySize, SM3);

    zero_stats_kernel<<<1, 128>>>();
    k1<<<B * (H / 32) * (W / 32), 256, SM1>>>(x, w1, h1);
    k2<<<B * 32 * 4, NT, SM2>>>(h1, w2, h2);
    k3<<<B * 32 * 4, NT, SM3>>>(h2, w3, out);
    bn_finalize_kernel<<<1, 64>>>(gamma, beta);
    bn_apply_kernel<<<(B * COUT * H * W / 4) / 256, 256>>>(out);
}